// round 4
// baseline (speedup 1.0000x reference)
#include <cuda_runtime.h>
#include <cstdint>

#define N_NODES 50000
#define DIM     64
#define CHUNKS  (DIM / 4)    // 16 float4 per row
#define TPE     4            // threads per edge (each handles 4 float4s)

// Accumulator [N_NODES, 16] float4 = 12.8 MB (L2-resident), 16B-aligned by type.
__device__ float4 g_Mv[(size_t)N_NODES * CHUNKS];

// 1 = indices stored as int64, 0 = int32
__device__ int g_is64;

__device__ __forceinline__ long long load_idx(const void* base, long long i, int is64) {
    if (is64) return __ldg(((const long long*)base) + i);
    return (long long)__ldg(((const int*)base) + i);
}

// ---------------------------------------------------------------------------
// Kernel 1: zero accumulator + PARALLEL index-dtype probe (first 64 threads
// of block 0 each check one entry, warp-ballot the verdict).
// ---------------------------------------------------------------------------
__global__ void zero_and_probe_kernel(int n4, const void* rev, int E) {
    int i = blockIdx.x * blockDim.x + threadIdx.x;
    if (i < n4) g_Mv[i] = make_float4(0.f, 0.f, 0.f, 0.f);

    if (blockIdx.x == 0 && threadIdx.x < 64) {
        const long long* r64 = (const long long*)rev;
        int k = threadIdx.x;
        int bad = 0;
        if (k < E) {
            long long v = r64[k];
            bad = (v < 0 || v >= (long long)E) ? 1 : 0;
        }
        unsigned m0 = __ballot_sync(0xFFFFFFFFu, bad);   // lanes 0-31 of each warp
        if ((threadIdx.x & 31) == 0) {
            // two warps participate; combine via atomic-free: each warp writes
            // only if it saw a bad entry; default set by warp 0 lane 0.
            if (threadIdx.x == 0) g_is64 = 1;            // provisional
            __threadfence();
            if (m0 != 0) g_is64 = 0;
        }
    }
}

// ---------------------------------------------------------------------------
// Kernel 2: scatter-add. 4 threads/edge, 4 float4 chunks each (c, c+4, c+8, c+12).
// Coalesced M reads; red.global.add.v4.f32 = one 16B L2-side RED per chunk.
// ---------------------------------------------------------------------------
__global__ void scatter_kernel(const float4* __restrict__ M4,
                               const void* __restrict__ ei,
                               int E) {
    int t = blockIdx.x * blockDim.x + threadIdx.x;
    int e = t >> 2;
    int c = t & 3;
    if (e >= E) return;

    int is64 = g_is64;
    long long d = load_idx(ei, (long long)E + e, is64);   // dest

    const float4* mrow = M4 + (size_t)e * CHUNKS;
    float4 v0 = __ldg(&mrow[c]);
    float4 v1 = __ldg(&mrow[c + 4]);
    float4 v2 = __ldg(&mrow[c + 8]);
    float4 v3 = __ldg(&mrow[c + 12]);

    float4* prow = g_Mv + (size_t)d * CHUNKS;
    asm volatile("red.global.add.v4.f32 [%0], {%1, %2, %3, %4};"
        :: "l"(__cvta_generic_to_global(prow + c)),
           "f"(v0.x), "f"(v0.y), "f"(v0.z), "f"(v0.w) : "memory");
    asm volatile("red.global.add.v4.f32 [%0], {%1, %2, %3, %4};"
        :: "l"(__cvta_generic_to_global(prow + c + 4)),
           "f"(v1.x), "f"(v1.y), "f"(v1.z), "f"(v1.w) : "memory");
    asm volatile("red.global.add.v4.f32 [%0], {%1, %2, %3, %4};"
        :: "l"(__cvta_generic_to_global(prow + c + 8)),
           "f"(v2.x), "f"(v2.y), "f"(v2.z), "f"(v2.w) : "memory");
    asm volatile("red.global.add.v4.f32 [%0], {%1, %2, %3, %4};"
        :: "l"(__cvta_generic_to_global(prow + c + 12)),
           "f"(v3.x), "f"(v3.y), "f"(v3.z), "f"(v3.w) : "memory");
}

// ---------------------------------------------------------------------------
// Kernel 3: out[e] = M_v[src[e]] - M[rev[e]]. 4 threads/edge, 4 chunks each.
// 8 independent loads in flight per thread hide the 234-262cyc L2-hit latency.
// M_v: evict-normal (stays L2-resident). M[rev]: __ldcs evict-first.
// out: __stcs streaming store.
// ---------------------------------------------------------------------------
__global__ void gather_kernel(const float4* __restrict__ M4,
                              const void* __restrict__ ei,
                              const void* __restrict__ rev,
                              float4* __restrict__ out,
                              int E) {
    int t = blockIdx.x * blockDim.x + threadIdx.x;
    int e = t >> 2;
    int c = t & 3;
    if (e >= E) return;

    int is64 = g_is64;
    long long s = load_idx(ei, e, is64);       // src
    long long r = load_idx(rev, e, is64);      // rev

    const float4* arow = g_Mv + (size_t)s * CHUNKS;
    const float4* brow = M4 + (size_t)r * CHUNKS;

    float4 a0 = __ldg(&arow[c]);
    float4 a1 = __ldg(&arow[c + 4]);
    float4 a2 = __ldg(&arow[c + 8]);
    float4 a3 = __ldg(&arow[c + 12]);
    float4 b0 = __ldcs(&brow[c]);
    float4 b1 = __ldcs(&brow[c + 4]);
    float4 b2 = __ldcs(&brow[c + 8]);
    float4 b3 = __ldcs(&brow[c + 12]);

    float4 o0, o1, o2, o3;
    o0.x = a0.x - b0.x; o0.y = a0.y - b0.y; o0.z = a0.z - b0.z; o0.w = a0.w - b0.w;
    o1.x = a1.x - b1.x; o1.y = a1.y - b1.y; o1.z = a1.z - b1.z; o1.w = a1.w - b1.w;
    o2.x = a2.x - b2.x; o2.y = a2.y - b2.y; o2.z = a2.z - b2.z; o2.w = a2.w - b2.w;
    o3.x = a3.x - b3.x; o3.y = a3.y - b3.y; o3.z = a3.z - b3.z; o3.w = a3.w - b3.w;

    float4* orow = out + (size_t)e * CHUNKS;
    __stcs(&orow[c], o0);
    __stcs(&orow[c + 4], o1);
    __stcs(&orow[c + 8], o2);
    __stcs(&orow[c + 12], o3);
}

// ---------------------------------------------------------------------------
// Launcher. Inputs (metadata order):
//   d_in[0] = M          float32     [E, 64]
//   d_in[1] = edge_index int64/int32 [2, E]  (row0=src, row1=dest)
//   d_in[2] = rev_index  int64/int32 [E]
//   d_in[3] = dim_size   scalar (50000, unused)
// Output: float32 [E, 64]
// ---------------------------------------------------------------------------
extern "C" void kernel_launch(void* const* d_in, const int* in_sizes, int n_in,
                              void* d_out, int out_size) {
    const float4* M4   = (const float4*)d_in[0];
    const void*   ei   = d_in[1];
    const void*   rev  = d_in[2];
    float4*       out4 = (float4*)d_out;

    const int E = in_sizes[2];

    {
        int n4 = N_NODES * CHUNKS;            // 800,000 float4s
        int tpb = 512;
        zero_and_probe_kernel<<<(n4 + tpb - 1) / tpb, tpb>>>(n4, rev, E);
    }
    {
        long long threads = (long long)E * TPE;
        int tpb = 256;
        int blocks = (int)((threads + tpb - 1) / tpb);
        scatter_kernel<<<blocks, tpb>>>(M4, ei, E);
    }
    {
        long long threads = (long long)E * TPE;
        int tpb = 256;
        int blocks = (int)((threads + tpb - 1) / tpb);
        gather_kernel<<<blocks, tpb>>>(M4, ei, rev, out4, E);
    }
}

// round 5
// speedup vs baseline: 1.0565x; 1.0565x over previous
#include <cuda_runtime.h>
#include <cstdint>

#define N_NODES 50000
#define DIM     64
#define CHUNKS  (DIM / 4)    // 16 float4 per row
#define TPE     8            // 8 threads/edge: one 128B line per load slot

// Accumulator [N_NODES, 16] float4 = 12.8 MB (L2-resident), 16B-aligned by type.
__device__ float4 g_Mv[(size_t)N_NODES * CHUNKS];

// 1 = indices stored as int64, 0 = int32
__device__ int g_is64;

__device__ __forceinline__ long long load_idx(const void* base, long long i, int is64) {
    if (is64) return __ldg(((const long long*)base) + i);
    return (long long)__ldg(((const int*)base) + i);
}

// Broadcast a 64-bit value from lane 0 of each 8-lane segment.
__device__ __forceinline__ long long bcast8(long long v) {
    return __shfl_sync(0xFFFFFFFFu, v, 0, 8);
}

// ---------------------------------------------------------------------------
// Kernel 1: zero accumulator + index-dtype probe (warp 0 of block 0).
// ---------------------------------------------------------------------------
__global__ void zero_and_probe_kernel(int n4, const void* rev, int E) {
    int i = blockIdx.x * blockDim.x + threadIdx.x;
    if (i < n4) g_Mv[i] = make_float4(0.f, 0.f, 0.f, 0.f);

    if (blockIdx.x == 0 && threadIdx.x < 32) {
        const long long* r64 = (const long long*)rev;
        int k = threadIdx.x;
        int bad = 0;
        if (k < E) {
            long long v = r64[k];
            bad = (v < 0 || v >= (long long)E) ? 1 : 0;
        }
        unsigned m = __ballot_sync(0xFFFFFFFFu, bad);
        if (threadIdx.x == 0) g_is64 = (m == 0) ? 1 : 0;
    }
}

// ---------------------------------------------------------------------------
// Kernel 2: scatter-add. 8 threads/edge, 2 float4 chunks each (c, c+8).
// Each warp load slot covers 4 edges x 128B full lines. One index LDG per
// edge-group (lane 0), shuffled to the other 7 lanes.
// ---------------------------------------------------------------------------
__global__ void scatter_kernel(const float4* __restrict__ M4,
                               const void* __restrict__ ei,
                               int E) {
    int t = blockIdx.x * blockDim.x + threadIdx.x;
    int e = t >> 3;
    int c = t & 7;
    if (e >= E) return;

    int is64 = g_is64;
    long long d = 0;
    if (c == 0) d = load_idx(ei, (long long)E + e, is64);   // dest
    d = bcast8(d);

    const float4* mrow = M4 + (size_t)e * CHUNKS;
    float4 v0 = __ldg(&mrow[c]);
    float4 v1 = __ldg(&mrow[c + 8]);

    float4* prow = g_Mv + (size_t)d * CHUNKS;
    asm volatile("red.global.add.v4.f32 [%0], {%1, %2, %3, %4};"
        :: "l"(__cvta_generic_to_global(prow + c)),
           "f"(v0.x), "f"(v0.y), "f"(v0.z), "f"(v0.w) : "memory");
    asm volatile("red.global.add.v4.f32 [%0], {%1, %2, %3, %4};"
        :: "l"(__cvta_generic_to_global(prow + c + 8)),
           "f"(v1.x), "f"(v1.y), "f"(v1.z), "f"(v1.w) : "memory");
}

// ---------------------------------------------------------------------------
// Kernel 3: out[e] = M_v[src[e]] - M[rev[e]]. 8 threads/edge, 2 chunks each.
// M_v: evict-normal (L2-resident). M[rev]: __ldcs evict-first.
// out: __stcs streaming store. Indices loaded once per edge, shuffled.
// ---------------------------------------------------------------------------
__global__ void gather_kernel(const float4* __restrict__ M4,
                              const void* __restrict__ ei,
                              const void* __restrict__ rev,
                              float4* __restrict__ out,
                              int E) {
    int t = blockIdx.x * blockDim.x + threadIdx.x;
    int e = t >> 3;
    int c = t & 7;
    if (e >= E) return;

    int is64 = g_is64;
    long long s = 0, r = 0;
    if (c == 0) {
        s = load_idx(ei, e, is64);     // src
        r = load_idx(rev, e, is64);    // rev
    }
    s = bcast8(s);
    r = bcast8(r);

    const float4* arow = g_Mv + (size_t)s * CHUNKS;
    const float4* brow = M4 + (size_t)r * CHUNKS;

    float4 a0 = __ldg(&arow[c]);
    float4 a1 = __ldg(&arow[c + 8]);
    float4 b0 = __ldcs(&brow[c]);
    float4 b1 = __ldcs(&brow[c + 8]);

    float4 o0, o1;
    o0.x = a0.x - b0.x; o0.y = a0.y - b0.y; o0.z = a0.z - b0.z; o0.w = a0.w - b0.w;
    o1.x = a1.x - b1.x; o1.y = a1.y - b1.y; o1.z = a1.z - b1.z; o1.w = a1.w - b1.w;

    float4* orow = out + (size_t)e * CHUNKS;
    __stcs(&orow[c], o0);
    __stcs(&orow[c + 8], o1);
}

// ---------------------------------------------------------------------------
// Launcher. Inputs (metadata order):
//   d_in[0] = M          float32     [E, 64]
//   d_in[1] = edge_index int64/int32 [2, E]  (row0=src, row1=dest)
//   d_in[2] = rev_index  int64/int32 [E]
//   d_in[3] = dim_size   scalar (50000, unused)
// Output: float32 [E, 64]
// ---------------------------------------------------------------------------
extern "C" void kernel_launch(void* const* d_in, const int* in_sizes, int n_in,
                              void* d_out, int out_size) {
    const float4* M4   = (const float4*)d_in[0];
    const void*   ei   = d_in[1];
    const void*   rev  = d_in[2];
    float4*       out4 = (float4*)d_out;

    const int E = in_sizes[2];

    {
        int n4 = N_NODES * CHUNKS;            // 800,000 float4s
        int tpb = 512;
        zero_and_probe_kernel<<<(n4 + tpb - 1) / tpb, tpb>>>(n4, rev, E);
    }
    {
        long long threads = (long long)E * TPE;
        int tpb = 256;
        int blocks = (int)((threads + tpb - 1) / tpb);
        scatter_kernel<<<blocks, tpb>>>(M4, ei, E);
    }
    {
        long long threads = (long long)E * TPE;
        int tpb = 256;
        int blocks = (int)((threads + tpb - 1) / tpb);
        gather_kernel<<<blocks, tpb>>>(M4, ei, rev, out4, E);
    }
}